// round 16
// baseline (speedup 1.0000x reference)
#include <cuda_runtime.h>
#include <cuda_fp16.h>
#include <math.h>
#include <stdint.h>

// Problem constants (fixed by setup_inputs)
#define BS_TOK 16384   // B*S
#define DIM    2048    // D
#define NEXP   64      // E
#define HID    1024    // D/2
#define NTILES 1024    // (BS_TOK/128) * (HID/128), bm-major
#define NCTA   148     // persistent CTAs for h1z

// Output layout (flattened tuple, fp32):
// idx[BS,2] | scores[BS,2] | probs_soft[BS,64] | importance[64] | load[64]
#define OFF_IDX    0
#define OFF_SCORES (BS_TOK * 2)
#define OFF_PROBS  (BS_TOK * 4)
#define OFF_IMP    (BS_TOK * 4 + BS_TOK * NEXP)
#define OFF_LOAD   (OFF_IMP + NEXP)

// Scratch (device globals: allocation-free)
__device__ __half g_xhi[(size_t)BS_TOK * DIM];          // fp16 hi of 1024*x
__device__ __half g_xlo[(size_t)BS_TOK * DIM];          // fp16 lo of 1024*x
__device__ __half g_w1h[(size_t)HID * DIM];             // fp16 of W1*gamma
__device__ __half g_wghi[(size_t)NEXP * DIM];           // fp16 hi of 1024*Wg
__device__ __half g_wglo[(size_t)NEXP * DIM];           // fp16 lo of 1024*Wg
__device__ float g_c1[HID];                             // sum_d gamma_d*W1[h,d]
__device__ float g_c2[HID];                             // sum_d beta_d*W1[h,d]
__device__ float g_mu[BS_TOK];
__device__ float g_rstd[BS_TOK];
__device__ float g_logits[(size_t)BS_TOK * NEXP];
__device__ float g_z[BS_TOK];                           // h1.W2 accumulator

// ---------------------------------------------------------------------------
// PTX helpers — family-portable only (no tcgen05: ptxas targets sm_103 base)
// ---------------------------------------------------------------------------
__device__ __forceinline__ uint32_t smem_u32(const void* p) {
    uint32_t a;
    asm("{ .reg .u64 t; cvta.to.shared.u64 t, %1; cvt.u32.u64 %0, t; }" : "=r"(a) : "l"(p));
    return a;
}
#define SWZ(o) ((o) ^ (((o) >> 3) & 0x70))
#define CP_ASYNC16(dst, src) \
    asm volatile("cp.async.cg.shared.global [%0], [%1], 16;" :: "r"(dst), "l"(src))
#define CP_COMMIT() asm volatile("cp.async.commit_group;" ::: "memory")
#define CP_WAIT1()  asm volatile("cp.async.wait_group 1;" ::: "memory")
#define CP_WAIT0()  asm volatile("cp.async.wait_group 0;" ::: "memory")

__device__ __forceinline__ void ldsm4(uint32_t* r, uint32_t addr) {
    asm volatile("ldmatrix.sync.aligned.m8n8.x4.shared.b16 {%0,%1,%2,%3}, [%4];"
                 : "=r"(r[0]), "=r"(r[1]), "=r"(r[2]), "=r"(r[3]) : "r"(addr));
}
__device__ __forceinline__ void mma_f16(float* c, const uint32_t* a, const uint32_t* b) {
    asm volatile(
        "mma.sync.aligned.m16n8k16.row.col.f32.f16.f16.f32 "
        "{%0,%1,%2,%3}, {%4,%5,%6,%7}, {%8,%9}, {%0,%1,%2,%3};"
        : "+f"(c[0]), "+f"(c[1]), "+f"(c[2]), "+f"(c[3])
        : "r"(a[0]), "r"(a[1]), "r"(a[2]), "r"(a[3]), "r"(b[0]), "r"(b[1]));
}

// ---------------------------------------------------------------------------
// Kernel 1: per-token stats (mu, rstd) + fp16 hi/lo split of 1024*x.
// Also zeroes g_z[token] and the importance/load accumulators (every replay).
// ---------------------------------------------------------------------------
__global__ void __launch_bounds__(256) prep_kernel(
    const float* __restrict__ x, float* __restrict__ out) {
    const int t = blockIdx.x, tid = threadIdx.x;
    const float4* xr = reinterpret_cast<const float4*>(x + (size_t)t * DIM);

    const float4 va = xr[2 * tid], vb = xr[2 * tid + 1];
    float f[8] = {va.x, va.y, va.z, va.w, vb.x, vb.y, vb.z, vb.w};

    float s = 0.f, sq = 0.f;
    #pragma unroll
    for (int j = 0; j < 8; j++) { s += f[j]; sq += f[j] * f[j]; }
    __shared__ float rs_[8], rq_[8];
    #pragma unroll
    for (int o = 16; o; o >>= 1) {
        s  += __shfl_down_sync(0xffffffffu, s, o);
        sq += __shfl_down_sync(0xffffffffu, sq, o);
    }
    if ((tid & 31) == 0) { rs_[tid >> 5] = s; rq_[tid >> 5] = sq; }
    __syncthreads();
    if (tid == 0) {
        float S = 0.f, Q = 0.f;
        #pragma unroll
        for (int i = 0; i < 8; i++) { S += rs_[i]; Q += rq_[i]; }
        float mu  = S * (1.f / DIM);
        float var = Q * (1.f / DIM) - mu * mu;
        g_mu[t]   = mu;
        g_rstd[t] = rsqrtf(var + 1e-5f);
        g_z[t]    = 0.f;
    }
    __half hi[8], lo[8];
    #pragma unroll
    for (int j = 0; j < 8; j++) {
        float g = f[j] * 1024.f;
        hi[j] = __float2half_rn(g);
        lo[j] = __float2half_rn(g - __half2float(hi[j]));
    }
    uint4 uh, ul;
    {
        __half2 a0 = __halves2half2(hi[0], hi[1]), a1 = __halves2half2(hi[2], hi[3]);
        __half2 a2 = __halves2half2(hi[4], hi[5]), a3 = __halves2half2(hi[6], hi[7]);
        uh.x = *reinterpret_cast<unsigned int*>(&a0);
        uh.y = *reinterpret_cast<unsigned int*>(&a1);
        uh.z = *reinterpret_cast<unsigned int*>(&a2);
        uh.w = *reinterpret_cast<unsigned int*>(&a3);
        __half2 b0 = __halves2half2(lo[0], lo[1]), b1 = __halves2half2(lo[2], lo[3]);
        __half2 b2 = __halves2half2(lo[4], lo[5]), b3 = __halves2half2(lo[6], lo[7]);
        ul.x = *reinterpret_cast<unsigned int*>(&b0);
        ul.y = *reinterpret_cast<unsigned int*>(&b1);
        ul.z = *reinterpret_cast<unsigned int*>(&b2);
        ul.w = *reinterpret_cast<unsigned int*>(&b3);
    }
    reinterpret_cast<uint4*>(g_xhi + (size_t)t * DIM)[tid] = uh;
    reinterpret_cast<uint4*>(g_xlo + (size_t)t * DIM)[tid] = ul;
    if (blockIdx.x == 0 && tid < 2 * NEXP) out[OFF_IMP + tid] = 0.f;
}

// ---------------------------------------------------------------------------
// Kernel 2: fused W1 row processing (block h): write fp16 W1*gamma row AND
// reduce c1[h] = sum gamma*W1, c2[h] = sum beta*W1 in one pass over W1.
// ---------------------------------------------------------------------------
__global__ void __launch_bounds__(256) wconv_cvec_kernel(
    const float* __restrict__ W1, const float* __restrict__ gamma,
    const float* __restrict__ beta) {
    const int h = blockIdx.x, tid = threadIdx.x;
    const float4* wr = reinterpret_cast<const float4*>(W1 + (size_t)h * DIM);
    const float4* gr = reinterpret_cast<const float4*>(gamma);
    const float4* br = reinterpret_cast<const float4*>(beta);

    const float4 wa = wr[2 * tid], wb = wr[2 * tid + 1];
    const float4 ga = gr[2 * tid], gb = gr[2 * tid + 1];
    const float4 ba = br[2 * tid], bb = br[2 * tid + 1];
    float w[8] = {wa.x, wa.y, wa.z, wa.w, wb.x, wb.y, wb.z, wb.w};
    float g[8] = {ga.x, ga.y, ga.z, ga.w, gb.x, gb.y, gb.z, gb.w};
    float b[8] = {ba.x, ba.y, ba.z, ba.w, bb.x, bb.y, bb.z, bb.w};

    float c1 = 0.f, c2 = 0.f;
    float wg[8];
    #pragma unroll
    for (int j = 0; j < 8; j++) {
        wg[j] = w[j] * g[j];
        c1 += wg[j];
        c2 += w[j] * b[j];
    }
    // write fp16 W1*gamma (uint4 = 8 halves)
    uint4 u;
    {
        __half2 p0 = __floats2half2_rn(wg[0], wg[1]);
        __half2 p1 = __floats2half2_rn(wg[2], wg[3]);
        __half2 p2 = __floats2half2_rn(wg[4], wg[5]);
        __half2 p3 = __floats2half2_rn(wg[6], wg[7]);
        u.x = *reinterpret_cast<unsigned int*>(&p0);
        u.y = *reinterpret_cast<unsigned int*>(&p1);
        u.z = *reinterpret_cast<unsigned int*>(&p2);
        u.w = *reinterpret_cast<unsigned int*>(&p3);
    }
    reinterpret_cast<uint4*>(g_w1h + (size_t)h * DIM)[tid] = u;

    __shared__ float r1[8], r2[8];
    #pragma unroll
    for (int o = 16; o; o >>= 1) {
        c1 += __shfl_down_sync(0xffffffffu, c1, o);
        c2 += __shfl_down_sync(0xffffffffu, c2, o);
    }
    if ((tid & 31) == 0) { r1[tid >> 5] = c1; r2[tid >> 5] = c2; }
    __syncthreads();
    if (tid == 0) {
        float a = 0.f, c = 0.f;
        #pragma unroll
        for (int i = 0; i < 8; i++) { a += r1[i]; c += r2[i]; }
        g_c1[h] = a; g_c2[h] = c;
    }
}

__global__ void __launch_bounds__(256) wgsplit_kernel(const float* __restrict__ Wg) {
    size_t i = (size_t)blockIdx.x * 256 + threadIdx.x;
    float w = Wg[i] * 1024.f;
    __half hi = __float2half_rn(w);
    __half lo = __float2half_rn(w - __half2float(hi));
    g_wghi[i] = hi; g_wglo[i] = lo;
}

// ---------------------------------------------------------------------------
// Kernel 3: logits = x @ Wg^T via 3xfp16 split MMA (unchanged, verified R9+).
// ---------------------------------------------------------------------------
__device__ __forceinline__ void copy_stageL(uint32_t st, const char* ahi, const char* alo,
                                            const char* bhi, const char* blo,
                                            int tid, size_t koff) {
    #pragma unroll
    for (int t = 0; t < 4; t++) {   // A: 128 rows x 8 units
        int u = tid + t * 256;
        int row = u >> 3, cu = u & 7;
        size_t g = (size_t)row * (DIM * 2) + koff + (size_t)cu * 16;
        uint32_t so = SWZ(row * 128 + cu * 16);
        CP_ASYNC16(st + so, ahi + g);
        CP_ASYNC16(st + 16384 + so, alo + g);
    }
    #pragma unroll
    for (int t = 0; t < 2; t++) {   // B: 64 rows x 8 units
        int u = tid + t * 256;
        int row = u >> 3, cu = u & 7;
        size_t g = (size_t)row * (DIM * 2) + koff + (size_t)cu * 16;
        uint32_t so = SWZ(row * 128 + cu * 16);
        CP_ASYNC16(st + 32768 + so, bhi + g);
        CP_ASYNC16(st + 40960 + so, blo + g);
    }
}

__global__ void __launch_bounds__(256, 1) logits_mma_kernel() {
    extern __shared__ char dynsmem[];
    const uint32_t raw  = smem_u32(dynsmem);
    const uint32_t base = (raw + 1023u) & ~1023u;

    const int tid = threadIdx.x, wid = tid >> 5, lane = tid & 31;
    const int warp_m = wid >> 1, warp_n = wid & 1;
    const int bm = blockIdx.x * 128;

    const char* ahi = reinterpret_cast<const char*>(g_xhi + (size_t)bm * DIM);
    const char* alo = reinterpret_cast<const char*>(g_xlo + (size_t)bm * DIM);
    const char* bhi = reinterpret_cast<const char*>(g_wghi);
    const char* blo = reinterpret_cast<const char*>(g_wglo);

    copy_stageL(base, ahi, alo, bhi, blo, tid, 0);           CP_COMMIT();
    copy_stageL(base + 49152, ahi, alo, bhi, blo, tid, 128); CP_COMMIT();

    float acc[2][4][4];
    #pragma unroll
    for (int a = 0; a < 2; a++)
        #pragma unroll
        for (int b = 0; b < 4; b++)
            #pragma unroll
            for (int c = 0; c < 4; c++) acc[a][b][c] = 0.f;

    #pragma unroll 1
    for (int i = 0; i < 32; i++) {
        if (i == 31) { CP_WAIT0(); } else { CP_WAIT1(); }
        __syncthreads();
        if (i + 2 < 32) {
            copy_stageL(base + ((i + 2) % 3) * 49152, ahi, alo, bhi, blo,
                        tid, (size_t)(i + 2) * 128);
            CP_COMMIT();
        }
        const uint32_t sA  = base + (i % 3) * 49152;
        const uint32_t sAl = sA + 16384;
        const uint32_t sB  = sA + 32768;
        const uint32_t sBl = sA + 40960;
        #pragma unroll
        for (int ks = 0; ks < 4; ks++) {
            uint32_t rah[2][4], ral[2][4];
            #pragma unroll
            for (int a = 0; a < 2; a++) {
                int row = warp_m * 32 + a * 16 + (lane & 15);
                int bc  = ks * 32 + (((lane >> 4) & 1) << 4);
                ldsm4(rah[a], sA + SWZ(row * 128 + bc));
                ldsm4(ral[a], sAl + SWZ(row * 128 + bc));
            }
            uint32_t rbh[4][2], rbl[4][2];
            #pragma unroll
            for (int bb = 0; bb < 4; bb += 2) {
                int nrow = warp_n * 32 + bb * 8 + (lane & 7) + ((lane >> 4) & 1) * 8;
                int kc   = ks * 32 + (((lane >> 3) & 1) << 4);
                uint32_t r[4];
                ldsm4(r, sB + SWZ(nrow * 128 + kc));
                rbh[bb][0] = r[0]; rbh[bb][1] = r[1];
                rbh[bb + 1][0] = r[2]; rbh[bb + 1][1] = r[3];
                ldsm4(r, sBl + SWZ(nrow * 128 + kc));
                rbl[bb][0] = r[0]; rbl[bb][1] = r[1];
                rbl[bb + 1][0] = r[2]; rbl[bb + 1][1] = r[3];
            }
            #pragma unroll
            for (int a = 0; a < 2; a++)
                #pragma unroll
                for (int b = 0; b < 4; b++) {
                    mma_f16(acc[a][b], rah[a], rbh[b]);
                    mma_f16(acc[a][b], rah[a], rbl[b]);
                    mma_f16(acc[a][b], ral[a], rbh[b]);
                }
        }
    }

    const float SC = 1.f / 1048576.f;   // 2^-20 (1024 * 1024 operand scaling)
    #pragma unroll
    for (int a = 0; a < 2; a++) {
        const int row = bm + warp_m * 32 + a * 16 + (lane >> 2);
        #pragma unroll
        for (int b = 0; b < 4; b++) {
            const int col = warp_n * 32 + b * 8 + 2 * (lane & 3);
            g_logits[(size_t)row * NEXP + col]           = acc[a][b][0] * SC;
            g_logits[(size_t)row * NEXP + col + 1]       = acc[a][b][1] * SC;
            g_logits[(size_t)(row + 8) * NEXP + col]     = acc[a][b][2] * SC;
            g_logits[(size_t)(row + 8) * NEXP + col + 1] = acc[a][b][3] * SC;
        }
    }
}

// ---------------------------------------------------------------------------
// Kernel 4: PERSISTENT fp16 mma GEMM acc = (1024*x) @ (W1*gamma)^T.
// 148 CTAs; each streams a contiguous range of the 1024 (bm-major) 128x128
// tiles through ONE continuous 3-stage/64KB cp.async pipeline (no drain at
// tile boundaries). Tile epilogue: exact LN affine + GELU + W2-dot with
// L1-hot global constants, then atomicAdd (REDG) into g_z[token].
// ---------------------------------------------------------------------------
__device__ __forceinline__ void copy_chunk(uint32_t st, int tile, int k, int tid) {
    const int bm = (tile >> 3) * 128;
    const int bn = (tile & 7) * 128;
    const char* ag = reinterpret_cast<const char*>(g_xhi + (size_t)bm * DIM);
    const char* bg = reinterpret_cast<const char*>(g_w1h + (size_t)bn * DIM);
    const size_t kb = (size_t)k * 256;
    #pragma unroll
    for (int h = 0; h < 2; h++) {
        #pragma unroll
        for (int t4 = 0; t4 < 4; t4++) {
            int u = tid + t4 * 256;
            int row = u >> 3, cu = u & 7;
            size_t g = (size_t)row * (DIM * 2) + kb + (size_t)h * 128 + (size_t)cu * 16;
            uint32_t so = SWZ(row * 128 + cu * 16);
            CP_ASYNC16(st + h * 16384 + so, ag + g);
            CP_ASYNC16(st + 32768 + h * 16384 + so, bg + g);
        }
    }
}

__device__ __forceinline__ void compute_half(uint32_t abase, uint32_t bbase,
                                             int warp_m, int warp_n, int lane,
                                             float acc[4][4][4]) {
    #pragma unroll
    for (int ks = 0; ks < 4; ks++) {
        uint32_t ra[4][4];
        #pragma unroll
        for (int a = 0; a < 4; a++) {
            int row = warp_m * 64 + a * 16 + (lane & 15);
            int bc  = ks * 32 + (((lane >> 4) & 1) << 4);
            ldsm4(ra[a], abase + SWZ(row * 128 + bc));
        }
        uint32_t rb[4][2];
        #pragma unroll
        for (int bb = 0; bb < 4; bb += 2) {
            int nrow = warp_n * 32 + bb * 8 + (lane & 7) + ((lane >> 4) & 1) * 8;
            int kc   = ks * 32 + (((lane >> 3) & 1) << 4);
            uint32_t r[4];
            ldsm4(r, bbase + SWZ(nrow * 128 + kc));
            rb[bb][0] = r[0];     rb[bb][1] = r[1];
            rb[bb + 1][0] = r[2]; rb[bb + 1][1] = r[3];
        }
        #pragma unroll
        for (int a = 0; a < 4; a++)
            #pragma unroll
            for (int b = 0; b < 4; b++)
                mma_f16(acc[a][b], ra[a], rb[b]);
    }
}

__global__ void __launch_bounds__(256, 1) h1z_kernel(const float* __restrict__ W2) {
    extern __shared__ char dynsmem[];
    const uint32_t raw  = smem_u32(dynsmem);
    const uint32_t base = (raw + 1023u) & ~1023u;

    const int tid = threadIdx.x, wid = tid >> 5, lane = tid & 31;
    const int warp_m = wid >> 2, warp_n = wid & 3;

    const int lo  = (int)(((long long)blockIdx.x * NTILES) / NCTA);
    const int hi  = (int)(((long long)(blockIdx.x + 1) * NTILES) / NCTA);
    const int nch = (hi - lo) * 16;

    copy_chunk(base,         lo,     0, tid); CP_COMMIT();
    copy_chunk(base + 65536, lo,     1, tid); CP_COMMIT();

    float acc[4][4][4];
    #pragma unroll
    for (int a = 0; a < 4; a++)
        #pragma unroll
        for (int b = 0; b < 4; b++)
            #pragma unroll
            for (int c = 0; c < 4; c++) acc[a][b][c] = 0.f;

    #pragma unroll 1
    for (int gc = 0; gc < nch; gc++) {
        if (gc == nch - 1) { CP_WAIT0(); } else { CP_WAIT1(); }
        __syncthreads();
        if (gc + 2 < nch) {
            const int ngc = gc + 2;
            copy_chunk(base + (ngc % 3) * 65536, lo + (ngc >> 4), ngc & 15, tid);
            CP_COMMIT();
        }
        const uint32_t st = base + (gc % 3) * 65536;
        compute_half(st, st + 32768, warp_m, warp_n, lane, acc);
        compute_half(st + 16384, st + 49152, warp_m, warp_n, lane, acc);

        if ((gc & 15) == 15) {
            // Tile epilogue: LN affine + GELU + W2-dot; REDG into g_z.
            const int tile = lo + (gc >> 4);
            const int bm = (tile >> 3) * 128;
            const int bn = (tile & 7) * 128;
            float z[8];
            #pragma unroll
            for (int j = 0; j < 8; j++) z[j] = 0.f;
            #pragma unroll
            for (int a = 0; a < 4; a++) {
                const int rg = bm + warp_m * 64 + a * 16 + (lane >> 2);
                const float rs0 = g_rstd[rg], mu0 = g_mu[rg];
                const float rs1 = g_rstd[rg + 8], mu1 = g_mu[rg + 8];
                #pragma unroll
                for (int b = 0; b < 4; b++) {
                    const int cg = bn + warp_n * 32 + b * 8 + 2 * (lane & 3);
                    const float w0 = W2[cg], w1 = W2[cg + 1];
                    const float c10 = g_c1[cg], c11 = g_c1[cg + 1];
                    const float c20 = g_c2[cg], c21 = g_c2[cg + 1];
                    float v0 = rs0 * (acc[a][b][0] * (1.f / 1024.f) - mu0 * c10) + c20;
                    float v1 = rs0 * (acc[a][b][1] * (1.f / 1024.f) - mu0 * c11) + c21;
                    float v2 = rs1 * (acc[a][b][2] * (1.f / 1024.f) - mu1 * c10) + c20;
                    float v3 = rs1 * (acc[a][b][3] * (1.f / 1024.f) - mu1 * c11) + c21;
                    v0 = 0.5f * v0 * (1.f + erff(v0 * 0.70710678118654752f));
                    v1 = 0.5f * v1 * (1.f + erff(v1 * 0.70710678118654752f));
                    v2 = 0.5f * v2 * (1.f + erff(v2 * 0.70710678118654752f));
                    v3 = 0.5f * v3 * (1.f + erff(v3 * 0.70710678118654752f));
                    z[a * 2 + 0] += v0 * w0 + v1 * w1;
                    z[a * 2 + 1] += v2 * w0 + v3 * w1;
                    acc[a][b][0] = 0.f; acc[a][b][1] = 0.f;
                    acc[a][b][2] = 0.f; acc[a][b][3] = 0.f;
                }
            }
            #pragma unroll
            for (int m = 1; m <= 2; m <<= 1)
                #pragma unroll
                for (int j = 0; j < 8; j++)
                    z[j] += __shfl_xor_sync(0xffffffffu, z[j], m);
            if ((lane & 3) == 0) {
                #pragma unroll
                for (int a = 0; a < 4; a++) {
                    const int rg = bm + warp_m * 64 + a * 16 + (lane >> 2);
                    atomicAdd(&g_z[rg], z[a * 2 + 0]);
                    atomicAdd(&g_z[rg + 8], z[a * 2 + 1]);
                }
            }
        }
    }
}

// ---------------------------------------------------------------------------
// Kernel 5: epilogue, 4 tokens per warp; z read directly from g_z.
// ---------------------------------------------------------------------------
__global__ void __launch_bounds__(256) epilogue_kernel(float* __restrict__ out) {
    __shared__ float s_imp[NEXP], s_load[NEXP];
    const int tid = threadIdx.x;
    if (tid < NEXP) s_imp[tid] = 0.f;
    else if (tid < 2 * NEXP) s_load[tid - NEXP] = 0.f;
    __syncthreads();

    const int w = tid >> 5, lane = tid & 31;
    float impacc0 = 0.f, impacc1 = 0.f;

    #pragma unroll 1
    for (int j = 0; j < 4; j++) {
        const int t = blockIdx.x * 32 + w * 4 + j;

        const float zp = g_z[t];
        const float sc = 1.f / (1.f + 1.f / (1.f + expf(-zp)));

        const float* lrow = g_logits + (size_t)t * NEXP;
        const float l0 = lrow[lane] * sc;
        const float l1 = lrow[lane + 32] * sc;

        float m = fmaxf(l0, l1);
        #pragma unroll
        for (int o = 16; o; o >>= 1) m = fmaxf(m, __shfl_xor_sync(0xffffffffu, m, o));
        const float e0 = expf(l0 - m), e1 = expf(l1 - m);
        float se = e0 + e1;
        #pragma unroll
        for (int o = 16; o; o >>= 1) se += __shfl_xor_sync(0xffffffffu, se, o);
        const float inv = 1.f / se;
        const float p0 = e0 * inv, p1 = e1 * inv;

        out[OFF_PROBS + (size_t)t * NEXP + lane]      = p0;
        out[OFF_PROBS + (size_t)t * NEXP + lane + 32] = p1;
        impacc0 += p0;
        impacc1 += p1;

        float v; int ei;
        if (l1 > l0) { v = l1; ei = lane + 32; } else { v = l0; ei = lane; }
        #pragma unroll
        for (int o = 16; o; o >>= 1) {
            float ov = __shfl_xor_sync(0xffffffffu, v, o);
            int   oi = __shfl_xor_sync(0xffffffffu, ei, o);
            if (ov > v || (ov == v && oi < ei)) { v = ov; ei = oi; }
        }
        const int i0 = ei;
        float a0 = (lane == i0)      ? -3.4e38f : l0;
        float a1 = (lane + 32 == i0) ? -3.4e38f : l1;
        if (a1 > a0) { v = a1; ei = lane + 32; } else { v = a0; ei = lane; }
        #pragma unroll
        for (int o = 16; o; o >>= 1) {
            float ov = __shfl_xor_sync(0xffffffffu, v, o);
            int   oi = __shfl_xor_sync(0xffffffffu, ei, o);
            if (ov > v || (ov == v && oi < ei)) { v = ov; ei = oi; }
        }
        const int i1 = ei;

        const float c0 = (i0 < 32) ? p0 : p1;
        const float pi0 = __shfl_sync(0xffffffffu, c0, i0 & 31);
        const float c1 = (i1 < 32) ? p0 : p1;
        const float pi1 = __shfl_sync(0xffffffffu, c1, i1 & 31);

        if (lane == 0) {
            const float s0 = (1.0f - pi0) + pi0;
            const float s1 = (1.0f - pi1) + pi1;
            const float sn = fmaxf(s0 + s1, 1e-9f);
            out[OFF_IDX + t * 2 + 0]    = (float)i0;
            out[OFF_IDX + t * 2 + 1]    = (float)i1;
            out[OFF_SCORES + t * 2 + 0] = s0 / sn;
            out[OFF_SCORES + t * 2 + 1] = s1 / sn;
            atomicAdd(&s_load[i0], 1.f);
            atomicAdd(&s_load[i1], 1.f);
        }
    }
    atomicAdd(&s_imp[lane], impacc0);
    atomicAdd(&s_imp[lane + 32], impacc1);
    __syncthreads();
    if (tid < NEXP)
        atomicAdd(&out[OFF_IMP + tid], s_imp[tid] * (1.f / BS_TOK));
    else if (tid < 2 * NEXP)
        atomicAdd(&out[OFF_LOAD + tid - NEXP], s_load[tid - NEXP] * (1.f / BS_TOK));
}

// ---------------------------------------------------------------------------
// kernel_launch: graph-capturable sequence.
// Inputs: x[B,S,D], Wg[E,D], gamma[D], beta[D], W1[H,D], W2[1,H] (fp32)
// ---------------------------------------------------------------------------
extern "C" void kernel_launch(void* const* d_in, const int* in_sizes, int n_in,
                              void* d_out, int out_size) {
    const float* x     = (const float*)d_in[0];
    const float* Wg    = (const float*)d_in[1];
    const float* gamma = (const float*)d_in[2];
    const float* beta  = (const float*)d_in[3];
    const float* W1    = (const float*)d_in[4];
    const float* W2    = (const float*)d_in[5];
    float* out = (float*)d_out;

    cudaFuncSetAttribute(h1z_kernel, cudaFuncAttributeMaxDynamicSharedMemorySize, 197632);
    cudaFuncSetAttribute(logits_mma_kernel, cudaFuncAttributeMaxDynamicSharedMemorySize, 148480);

    // 1) stats + fp16 x split + zero z/accumulators
    prep_kernel<<<BS_TOK, 256>>>(x, out);
    // 2) fused W1 conversion + LN affine constants; Wg split
    wconv_cvec_kernel<<<HID, 256>>>(W1, gamma, beta);
    wgsplit_kernel<<<(NEXP * DIM) / 256, 256>>>(Wg);
    // 3) logits via 3xfp16 split MMA
    logits_mma_kernel<<<BS_TOK / 128, 256, 148480>>>();
    // 4) persistent fp16 mma h1 GEMM + LN affine + GELU + W2-dot -> g_z
    h1z_kernel<<<NCTA, 256, 197632>>>(W2);
    // 5) softmax / top-2 / outputs
    epilogue_kernel<<<BS_TOK / 32, 256>>>(out);

    (void)in_sizes; (void)n_in; (void)out_size;
}